// round 3
// baseline (speedup 1.0000x reference)
#include <cuda_runtime.h>
#include <cstdint>

#define NXG   512
#define NYG   512
#define NCELL (NXG * NYG)   // 262144
#define MAXB  8             // scratch sized for up to 8 batches

// scratch: inverse map cell -> (global pillar index + 1), 0 = empty.
// Initialized by cudaMemsetAsync(0) each launch (HW memset path).
__device__ int g_inv[MAXB * NCELL];

// ---------------------------------------------------------------------------
// Kernel B: scatter (bp+1) into inv map for valid pillars
__global__ void build_inv_kernel(const int* __restrict__ coords,
                                 const int* __restrict__ mask,
                                 int BP, int P)
{
    int bp = blockIdx.x * blockDim.x + threadIdx.x;
    if (bp >= BP) return;
    if (mask[bp] <= 0) return;
    int ix = coords[2 * bp + 0];
    int iy = coords[2 * bp + 1];
    int b  = bp / P;
    g_inv[b * NCELL + iy * NXG + ix] = bp + 1;
}

// ---------------------------------------------------------------------------
// Kernel C: write full BEV output as coalesced float4 streaming stores.
// Block = 256 threads, each thread owns 8 consecutive cells of batch
// blockIdx.y (2x int4 inv loads), loops over all C channels writing
// 2x float4 per iteration. Streaming hint keeps emb resident in L2.
__global__ void __launch_bounds__(256)
bev_write_kernel(const float* __restrict__ emb,
                 float*       __restrict__ out,
                 int C)
{
    int b        = blockIdx.y;
    int cellBase = (blockIdx.x * 256 + threadIdx.x) * 8;   // 8 cells per thread

    const int4 pa = __ldg((const int4*)(&g_inv[b * NCELL + cellBase]));
    const int4 pb = __ldg((const int4*)(&g_inv[b * NCELL + cellBase + 4]));

    float* obase = out + ((long long)b * C) * NCELL + cellBase;

    const float* e0 = pa.x ? emb + (long long)(pa.x - 1) * C : nullptr;
    const float* e1 = pa.y ? emb + (long long)(pa.y - 1) * C : nullptr;
    const float* e2 = pa.z ? emb + (long long)(pa.z - 1) * C : nullptr;
    const float* e3 = pa.w ? emb + (long long)(pa.w - 1) * C : nullptr;
    const float* e4 = pb.x ? emb + (long long)(pb.x - 1) * C : nullptr;
    const float* e5 = pb.y ? emb + (long long)(pb.y - 1) * C : nullptr;
    const float* e6 = pb.z ? emb + (long long)(pb.z - 1) * C : nullptr;
    const float* e7 = pb.w ? emb + (long long)(pb.w - 1) * C : nullptr;

    #pragma unroll 4
    for (int c = 0; c < C; c++) {
        float4 va, vb;
        va.x = e0 ? __ldg(e0 + c) : 0.0f;
        va.y = e1 ? __ldg(e1 + c) : 0.0f;
        va.z = e2 ? __ldg(e2 + c) : 0.0f;
        va.w = e3 ? __ldg(e3 + c) : 0.0f;
        vb.x = e4 ? __ldg(e4 + c) : 0.0f;
        vb.y = e5 ? __ldg(e5 + c) : 0.0f;
        vb.z = e6 ? __ldg(e6 + c) : 0.0f;
        vb.w = e7 ? __ldg(e7 + c) : 0.0f;
        float* op = obase + (long long)c * NCELL;
        __stcs((float4*)op,     va);
        __stcs((float4*)(op+4), vb);
    }
}

// ---------------------------------------------------------------------------
extern "C" void kernel_launch(void* const* d_in, const int* in_sizes, int n_in,
                              void* d_out, int out_size)
{
    const float* emb    = (const float*)d_in[0];   // [B, P, C] f32
    const int*   coords = (const int*)  d_in[1];   // [B, P, 2] i32
    const int*   mask   = (const int*)  d_in[2];   // [B, P]    i32

    int BP = in_sizes[2];                 // B*P
    int C  = in_sizes[0] / BP;            // 64
    int B  = out_size / (C * NCELL);      // 4
    int P  = BP / B;

    float* out = (float*)d_out;

    // A) inv = 0 via HW memset (0 == empty, entries are bp+1)
    void* inv_ptr = nullptr;
    cudaGetSymbolAddress(&inv_ptr, g_inv);
    cudaMemsetAsync(inv_ptr, 0, (size_t)B * NCELL * sizeof(int), 0);

    // B) scatter pillar indices
    {
        int threads = 256;
        build_inv_kernel<<<(BP + threads - 1) / threads, threads>>>(coords, mask, BP, P);
    }
    // C) full coalesced output write (8 cells/thread)
    {
        dim3 grid(NCELL / (256 * 8), B);   // 128 x B blocks
        bev_write_kernel<<<grid, 256>>>(emb, out, C);
    }
}

// round 4
// speedup vs baseline: 1.6318x; 1.6318x over previous
#include <cuda_runtime.h>
#include <cstdint>

#define NXG   512
#define NYG   512
#define NCELL (NXG * NYG)   // 262144
#define MAXB  8             // scratch sized for up to 8 batches

// scratch: inverse map cell -> (global pillar index + 1), 0 = empty.
// Initialized by cudaMemsetAsync(0) each launch (HW memset path).
__device__ int g_inv[MAXB * NCELL];

// ---------------------------------------------------------------------------
// Kernel B: scatter (bp+1) into inv map for valid pillars
__global__ void build_inv_kernel(const int* __restrict__ coords,
                                 const int* __restrict__ mask,
                                 int BP, int P)
{
    int bp = blockIdx.x * blockDim.x + threadIdx.x;
    if (bp >= BP) return;
    if (mask[bp] <= 0) return;
    int ix = coords[2 * bp + 0];
    int iy = coords[2 * bp + 1];
    int b  = bp / P;
    g_inv[b * NCELL + iy * NXG + ix] = bp + 1;
}

// ---------------------------------------------------------------------------
// Kernel C (R2-proven version): write full BEV output as coalesced float4
// streams. Block = 256 threads, handles 1024 consecutive cells of batch
// blockIdx.y, loops over all C channels. 4 cells/thread, plain stores —
// high occupancy is what feeds the store pipe here.
__global__ void __launch_bounds__(256)
bev_write_kernel(const float* __restrict__ emb,
                 float*       __restrict__ out,
                 int C)
{
    int b        = blockIdx.y;
    int cellBase = (blockIdx.x * 256 + threadIdx.x) * 4;   // 4 cells per thread

    const int4 pi = *(const int4*)(&g_inv[b * NCELL + cellBase]);

    float* obase = out + ((long long)b * C) * NCELL + cellBase;

    const float* e0 = pi.x ? emb + (long long)(pi.x - 1) * C : nullptr;
    const float* e1 = pi.y ? emb + (long long)(pi.y - 1) * C : nullptr;
    const float* e2 = pi.z ? emb + (long long)(pi.z - 1) * C : nullptr;
    const float* e3 = pi.w ? emb + (long long)(pi.w - 1) * C : nullptr;

    #pragma unroll 8
    for (int c = 0; c < C; c++) {
        float4 v;
        v.x = e0 ? e0[c] : 0.0f;
        v.y = e1 ? e1[c] : 0.0f;
        v.z = e2 ? e2[c] : 0.0f;
        v.w = e3 ? e3[c] : 0.0f;
        *(float4*)(obase + (long long)c * NCELL) = v;
    }
}

// ---------------------------------------------------------------------------
extern "C" void kernel_launch(void* const* d_in, const int* in_sizes, int n_in,
                              void* d_out, int out_size)
{
    const float* emb    = (const float*)d_in[0];   // [B, P, C] f32
    const int*   coords = (const int*)  d_in[1];   // [B, P, 2] i32
    const int*   mask   = (const int*)  d_in[2];   // [B, P]    i32

    int BP = in_sizes[2];                 // B*P
    int C  = in_sizes[0] / BP;            // 64
    int B  = out_size / (C * NCELL);      // 4
    int P  = BP / B;

    float* out = (float*)d_out;

    // A) inv = 0 via HW memset (0 == empty, entries are bp+1)
    void* inv_ptr = nullptr;
    cudaGetSymbolAddress(&inv_ptr, g_inv);
    cudaMemsetAsync(inv_ptr, 0, (size_t)B * NCELL * sizeof(int), 0);

    // B) scatter pillar indices
    {
        int threads = 256;
        build_inv_kernel<<<(BP + threads - 1) / threads, threads>>>(coords, mask, BP, P);
    }
    // C) full coalesced output write (4 cells/thread, R2-proven)
    {
        dim3 grid(NCELL / 1024, B);   // 256 x B blocks
        bev_write_kernel<<<grid, 256>>>(emb, out, C);
    }
}

// round 5
// speedup vs baseline: 1.6734x; 1.0255x over previous
#include <cuda_runtime.h>
#include <cstdint>

#define NXG    512
#define NYG    512
#define NCELL  (NXG * NYG)   // 262144
#define MAXB   8             // scratch sized for up to 8 batches
#define CCHUNK 16            // channels per block (C=64 -> 4 chunks)

// scratch: inverse map cell -> (global pillar index + 1), 0 = empty.
// Initialized by cudaMemsetAsync(0) each launch (HW memset path).
__device__ int g_inv[MAXB * NCELL];

// ---------------------------------------------------------------------------
// Kernel B: scatter (bp+1) into inv map for valid pillars
__global__ void build_inv_kernel(const int* __restrict__ coords,
                                 const int* __restrict__ mask,
                                 int BP, int P)
{
    int bp = blockIdx.x * blockDim.x + threadIdx.x;
    if (bp >= BP) return;
    if (mask[bp] <= 0) return;
    int ix = coords[2 * bp + 0];
    int iy = coords[2 * bp + 1];
    int b  = bp / P;
    g_inv[b * NCELL + iy * NXG + ix] = bp + 1;
}

// ---------------------------------------------------------------------------
// Kernel C: write full BEV output as coalesced float4 streams.
// grid = (NCELL/1024, C/CCHUNK, B). Each block owns 1024 consecutive cells
// of one batch and writes CCHUNK channel planes. 4x more blocks than R4 ->
// more warps in flight to hide store latency.
__global__ void __launch_bounds__(256)
bev_write_kernel(const float* __restrict__ emb,
                 float*       __restrict__ out,
                 int C)
{
    int b        = blockIdx.z;
    int c0       = blockIdx.y * CCHUNK;
    int cellBase = (blockIdx.x * 256 + threadIdx.x) * 4;   // 4 cells per thread

    const int4 pi = *(const int4*)(&g_inv[b * NCELL + cellBase]);

    float* obase = out + ((long long)b * C + c0) * NCELL + cellBase;

    const float* e0 = pi.x ? emb + (long long)(pi.x - 1) * C + c0 : nullptr;
    const float* e1 = pi.y ? emb + (long long)(pi.y - 1) * C + c0 : nullptr;
    const float* e2 = pi.z ? emb + (long long)(pi.z - 1) * C + c0 : nullptr;
    const float* e3 = pi.w ? emb + (long long)(pi.w - 1) * C + c0 : nullptr;

    #pragma unroll
    for (int c = 0; c < CCHUNK; c++) {
        float4 v;
        v.x = e0 ? e0[c] : 0.0f;
        v.y = e1 ? e1[c] : 0.0f;
        v.z = e2 ? e2[c] : 0.0f;
        v.w = e3 ? e3[c] : 0.0f;
        *(float4*)(obase + (long long)c * NCELL) = v;
    }
}

// ---------------------------------------------------------------------------
extern "C" void kernel_launch(void* const* d_in, const int* in_sizes, int n_in,
                              void* d_out, int out_size)
{
    const float* emb    = (const float*)d_in[0];   // [B, P, C] f32
    const int*   coords = (const int*)  d_in[1];   // [B, P, 2] i32
    const int*   mask   = (const int*)  d_in[2];   // [B, P]    i32

    int BP = in_sizes[2];                 // B*P
    int C  = in_sizes[0] / BP;            // 64
    int B  = out_size / (C * NCELL);      // 4
    int P  = BP / B;

    float* out = (float*)d_out;

    // A) inv = 0 via HW memset (0 == empty, entries are bp+1)
    void* inv_ptr = nullptr;
    cudaGetSymbolAddress(&inv_ptr, g_inv);
    cudaMemsetAsync(inv_ptr, 0, (size_t)B * NCELL * sizeof(int), 0);

    // B) scatter pillar indices
    {
        int threads = 256;
        build_inv_kernel<<<(BP + threads - 1) / threads, threads>>>(coords, mask, BP, P);
    }
    // C) full coalesced output write, C split across blocks
    {
        dim3 grid(NCELL / 1024, C / CCHUNK, B);   // 256 x 4 x B blocks
        bev_write_kernel<<<grid, 256>>>(emb, out, C);
    }
}

// round 6
// speedup vs baseline: 2.0035x; 1.1973x over previous
#include <cuda_runtime.h>
#include <cstdint>

#define NXG    512
#define NYG    512
#define NCELL  (NXG * NYG)   // 262144
#define MAXB   8             // scratch sized for up to 8 batches
#define CCHUNK 16            // channels per block (C=64 -> 4 chunks)

// Inverse map cell -> (global pillar index + 1), 0 = empty.
// NEVER zeroed at runtime: entries are validated against current inputs in
// bev_write, so stale entries are either rejected or provably identical to
// what this call's build_inv writes. Zero-initialized at module load.
__device__ int g_inv[MAXB * NCELL];

// ---------------------------------------------------------------------------
// Kernel B: scatter (bp+1) into inv map for valid pillars
__global__ void build_inv_kernel(const int* __restrict__ coords,
                                 const int* __restrict__ mask,
                                 int BP, int P)
{
    int bp = blockIdx.x * blockDim.x + threadIdx.x;
    if (bp >= BP) return;
    if (mask[bp] <= 0) return;
    int ix = coords[2 * bp + 0];
    int iy = coords[2 * bp + 1];
    int b  = bp / P;
    g_inv[b * NCELL + iy * NXG + ix] = bp + 1;
}

// ---------------------------------------------------------------------------
// Validate an inv entry against CURRENT inputs. Returns emb row ptr or null.
__device__ __forceinline__
const float* validate(int v, int cell, int b,
                      const float* __restrict__ emb,
                      const int*   __restrict__ coords,
                      const int*   __restrict__ mask,
                      int BP, int P, int C, int c0)
{
    if (v == 0) return nullptr;
    int bp = v - 1;
    if (bp >= BP) return nullptr;
    if (bp / P != b) return nullptr;
    if (mask[bp] <= 0) return nullptr;
    int ix = coords[2 * bp + 0];
    int iy = coords[2 * bp + 1];
    if ((iy * NXG + ix) != cell) return nullptr;
    return emb + (long long)bp * C + c0;
}

// ---------------------------------------------------------------------------
// Kernel C: write full BEV output as coalesced float4 streaming stores.
// grid = (NCELL/1024, C/CCHUNK, B). 4 cells/thread, CCHUNK channel planes.
__global__ void __launch_bounds__(256)
bev_write_kernel(const float* __restrict__ emb,
                 const int*   __restrict__ coords,
                 const int*   __restrict__ mask,
                 float*       __restrict__ out,
                 int BP, int P, int C)
{
    int b        = blockIdx.z;
    int c0       = blockIdx.y * CCHUNK;
    int cellBase = (blockIdx.x * 256 + threadIdx.x) * 4;   // 4 cells per thread

    const int4 pi = *(const int4*)(&g_inv[b * NCELL + cellBase]);

    float* obase = out + ((long long)b * C + c0) * NCELL + cellBase;

    const float* e0 = validate(pi.x, cellBase + 0, b, emb, coords, mask, BP, P, C, c0);
    const float* e1 = validate(pi.y, cellBase + 1, b, emb, coords, mask, BP, P, C, c0);
    const float* e2 = validate(pi.z, cellBase + 2, b, emb, coords, mask, BP, P, C, c0);
    const float* e3 = validate(pi.w, cellBase + 3, b, emb, coords, mask, BP, P, C, c0);

    #pragma unroll
    for (int c = 0; c < CCHUNK; c++) {
        float4 v;
        v.x = e0 ? e0[c] : 0.0f;
        v.y = e1 ? e1[c] : 0.0f;
        v.z = e2 ? e2[c] : 0.0f;
        v.w = e3 ? e3[c] : 0.0f;
        __stcs((float4*)(obase + (long long)c * NCELL), v);
    }
}

// ---------------------------------------------------------------------------
extern "C" void kernel_launch(void* const* d_in, const int* in_sizes, int n_in,
                              void* d_out, int out_size)
{
    const float* emb    = (const float*)d_in[0];   // [B, P, C] f32
    const int*   coords = (const int*)  d_in[1];   // [B, P, 2] i32
    const int*   mask   = (const int*)  d_in[2];   // [B, P]    i32

    int BP = in_sizes[2];                 // B*P
    int C  = in_sizes[0] / BP;            // 64
    int B  = out_size / (C * NCELL);      // 4
    int P  = BP / B;

    float* out = (float*)d_out;

    // B) scatter pillar indices (no zero-init needed: entries validated)
    {
        int threads = 256;
        build_inv_kernel<<<(BP + threads - 1) / threads, threads>>>(coords, mask, BP, P);
    }
    // C) full coalesced output write, C split across blocks, streaming stores
    {
        dim3 grid(NCELL / 1024, C / CCHUNK, B);   // 256 x 4 x B blocks
        bev_write_kernel<<<grid, 256>>>(emb, coords, mask, out, BP, P, C);
    }
}

// round 7
// speedup vs baseline: 2.0050x; 1.0007x over previous
#include <cuda_runtime.h>
#include <cstdint>

#define NXG    512
#define NYG    512
#define NCELL  (NXG * NYG)   // 262144
#define MAXB   8             // scratch sized for up to 8 batches
#define CCHUNK 16            // channels per block (C=64 -> 4 chunks)

// Inverse map cell -> (global pillar index + 1), 0 = empty.
// NEVER zeroed at runtime: entries are validated against current inputs in
// bev_write (stale entries are rejected or provably identical to what this
// call writes). Zero-initialized at module load.
// uint16 primary map (BP+1 <= 65535); int32 fallback for larger BP.
__device__ unsigned short g_inv16[MAXB * NCELL];
__device__ int            g_inv32[MAXB * NCELL];

// ---------------------------------------------------------------------------
template <typename T>
__global__ void build_inv_kernel(const int* __restrict__ coords,
                                 const int* __restrict__ mask,
                                 T* __restrict__ inv,
                                 int BP, int P)
{
    int bp = blockIdx.x * blockDim.x + threadIdx.x;
    if (bp >= BP) return;
    if (mask[bp] <= 0) return;
    int ix = coords[2 * bp + 0];
    int iy = coords[2 * bp + 1];
    int b  = bp / P;
    inv[b * NCELL + iy * NXG + ix] = (T)(bp + 1);
}

// ---------------------------------------------------------------------------
// Validate an inv entry against CURRENT inputs. Returns emb row ptr or null.
__device__ __forceinline__
const float* validate(int v, int cell, int b,
                      const float* __restrict__ emb,
                      const int*   __restrict__ coords,
                      const int*   __restrict__ mask,
                      int BP, int P, int C, int c0)
{
    if (v == 0) return nullptr;
    int bp = v - 1;
    if (bp >= BP) return nullptr;
    if (bp / P != b) return nullptr;
    if (mask[bp] <= 0) return nullptr;
    int ix = coords[2 * bp + 0];
    int iy = coords[2 * bp + 1];
    if ((iy * NXG + ix) != cell) return nullptr;
    return emb + (long long)bp * C + c0;
}

// ---------------------------------------------------------------------------
// Kernel C: write full BEV output as coalesced float4 streaming stores.
// grid = (NCELL/1024, C/CCHUNK, B). 4 cells/thread, CCHUNK channel planes.
template <typename T>
__global__ void __launch_bounds__(256)
bev_write_kernel(const float* __restrict__ emb,
                 const int*   __restrict__ coords,
                 const int*   __restrict__ mask,
                 const T*     __restrict__ inv,
                 float*       __restrict__ out,
                 int BP, int P, int C)
{
    int b        = blockIdx.z;
    int c0       = blockIdx.y * CCHUNK;
    int cellBase = (blockIdx.x * 256 + threadIdx.x) * 4;   // 4 cells per thread

    int v0, v1, v2, v3;
    if (sizeof(T) == 2) {
        const ushort4 pi = *(const ushort4*)(&inv[b * NCELL + cellBase]);
        v0 = pi.x; v1 = pi.y; v2 = pi.z; v3 = pi.w;
    } else {
        const int4 pi = *(const int4*)(&inv[b * NCELL + cellBase]);
        v0 = pi.x; v1 = pi.y; v2 = pi.z; v3 = pi.w;
    }

    float* obase = out + ((long long)b * C + c0) * NCELL + cellBase;

    const float* e0 = validate(v0, cellBase + 0, b, emb, coords, mask, BP, P, C, c0);
    const float* e1 = validate(v1, cellBase + 1, b, emb, coords, mask, BP, P, C, c0);
    const float* e2 = validate(v2, cellBase + 2, b, emb, coords, mask, BP, P, C, c0);
    const float* e3 = validate(v3, cellBase + 3, b, emb, coords, mask, BP, P, C, c0);

    #pragma unroll
    for (int c = 0; c < CCHUNK; c++) {
        float4 v;
        v.x = e0 ? e0[c] : 0.0f;
        v.y = e1 ? e1[c] : 0.0f;
        v.z = e2 ? e2[c] : 0.0f;
        v.w = e3 ? e3[c] : 0.0f;
        __stcs((float4*)(obase + (long long)c * NCELL), v);
    }
}

// ---------------------------------------------------------------------------
extern "C" void kernel_launch(void* const* d_in, const int* in_sizes, int n_in,
                              void* d_out, int out_size)
{
    const float* emb    = (const float*)d_in[0];   // [B, P, C] f32
    const int*   coords = (const int*)  d_in[1];   // [B, P, 2] i32
    const int*   mask   = (const int*)  d_in[2];   // [B, P]    i32

    int BP = in_sizes[2];                 // B*P
    int C  = in_sizes[0] / BP;            // 64
    int B  = out_size / (C * NCELL);      // 4
    int P  = BP / B;

    float* out = (float*)d_out;

    int threads = 256;
    int bblocks = (BP + threads - 1) / threads;
    dim3 cgrid(NCELL / 1024, C / CCHUNK, B);

    if (BP + 1 <= 65535) {
        unsigned short* inv = nullptr;
        cudaGetSymbolAddress((void**)&inv, g_inv16);
        build_inv_kernel<unsigned short><<<bblocks, threads>>>(coords, mask, inv, BP, P);
        bev_write_kernel<unsigned short><<<cgrid, 256>>>(emb, coords, mask, inv, out, BP, P, C);
    } else {
        int* inv = nullptr;
        cudaGetSymbolAddress((void**)&inv, g_inv32);
        build_inv_kernel<int><<<bblocks, threads>>>(coords, mask, inv, BP, P);
        bev_write_kernel<int><<<cgrid, 256>>>(emb, coords, mask, inv, out, BP, P, C);
    }
}

// round 8
// speedup vs baseline: 2.0973x; 1.0461x over previous
#include <cuda_runtime.h>
#include <cstdint>

#define NXG    512
#define NYG    512
#define NCELL  (NXG * NYG)   // 262144
#define MAXB   8             // scratch sized for up to 8 batches
#define CCHUNK 8             // channels per block (C=64 -> 8 chunks)

// Inverse map cell -> (global pillar index + 1), 0 = empty.
// NEVER zeroed at runtime: entries are validated against current inputs in
// bev_write (stale entries are rejected or provably identical to what this
// call writes). Zero-initialized at module load.
__device__ unsigned short g_inv16[MAXB * NCELL];
__device__ int            g_inv32[MAXB * NCELL];

// ---------------------------------------------------------------------------
template <typename T>
__global__ void build_inv_kernel(const int* __restrict__ coords,
                                 const int* __restrict__ mask,
                                 T* __restrict__ inv,
                                 int BP, int P)
{
    int bp = blockIdx.x * blockDim.x + threadIdx.x;
    if (bp < BP && mask[bp] > 0) {
        int ix = coords[2 * bp + 0];
        int iy = coords[2 * bp + 1];
        int b  = bp / P;
        inv[b * NCELL + iy * NXG + ix] = (T)(bp + 1);
    }
#if __CUDA_ARCH__ >= 900
    cudaTriggerProgrammaticLaunchCompletion();
#endif
}

// ---------------------------------------------------------------------------
// Validate an inv entry against CURRENT inputs. Returns emb row ptr or null.
__device__ __forceinline__
const float* validate(int v, int cell, int b,
                      const float* __restrict__ emb,
                      const int*   __restrict__ coords,
                      const int*   __restrict__ mask,
                      int BP, int P, int C, int c0)
{
    if (v == 0) return nullptr;
    int bp = v - 1;
    if (bp >= BP) return nullptr;
    if (bp / P != b) return nullptr;
    if (mask[bp] <= 0) return nullptr;
    int ix = coords[2 * bp + 0];
    int iy = coords[2 * bp + 1];
    if ((iy * NXG + ix) != cell) return nullptr;
    return emb + (long long)bp * C + c0;
}

// ---------------------------------------------------------------------------
// Kernel C: write full BEV output as coalesced float4 streaming stores.
// grid = (NCELL/1024, C/CCHUNK, B). 4 cells/thread, CCHUNK channel planes.
// Launched with PDL: waits on build_inv only at the inv read.
template <typename T>
__global__ void __launch_bounds__(256)
bev_write_kernel(const float* __restrict__ emb,
                 const int*   __restrict__ coords,
                 const int*   __restrict__ mask,
                 const T*     __restrict__ inv,
                 float*       __restrict__ out,
                 int BP, int P, int C)
{
    int b        = blockIdx.z;
    int c0       = blockIdx.y * CCHUNK;
    int cellBase = (blockIdx.x * 256 + threadIdx.x) * 4;   // 4 cells per thread

    float* obase = out + ((long long)b * C + c0) * NCELL + cellBase;

#if __CUDA_ARCH__ >= 900
    cudaGridDependencySynchronize();   // build_inv results must be visible
#endif

    int v0, v1, v2, v3;
    if (sizeof(T) == 2) {
        const ushort4 pi = *(const ushort4*)(&inv[b * NCELL + cellBase]);
        v0 = pi.x; v1 = pi.y; v2 = pi.z; v3 = pi.w;
    } else {
        const int4 pi = *(const int4*)(&inv[b * NCELL + cellBase]);
        v0 = pi.x; v1 = pi.y; v2 = pi.z; v3 = pi.w;
    }

    const float* e0 = validate(v0, cellBase + 0, b, emb, coords, mask, BP, P, C, c0);
    const float* e1 = validate(v1, cellBase + 1, b, emb, coords, mask, BP, P, C, c0);
    const float* e2 = validate(v2, cellBase + 2, b, emb, coords, mask, BP, P, C, c0);
    const float* e3 = validate(v3, cellBase + 3, b, emb, coords, mask, BP, P, C, c0);

    #pragma unroll
    for (int c = 0; c < CCHUNK; c++) {
        float4 v;
        v.x = e0 ? e0[c] : 0.0f;
        v.y = e1 ? e1[c] : 0.0f;
        v.z = e2 ? e2[c] : 0.0f;
        v.w = e3 ? e3[c] : 0.0f;
        __stcs((float4*)(obase + (long long)c * NCELL), v);
    }
}

// ---------------------------------------------------------------------------
template <typename T>
static void launch_path(const float* emb, const int* coords, const int* mask,
                        T* inv, float* out, int BP, int P, int C, int B)
{
    int threads = 256;
    int bblocks = (BP + threads - 1) / threads;
    build_inv_kernel<T><<<bblocks, threads>>>(coords, mask, inv, BP, P);

    // bev_write with programmatic dependent launch: overlaps with build_inv tail
    cudaLaunchAttribute attr[1];
    attr[0].id = cudaLaunchAttributeProgrammaticStreamSerialization;
    attr[0].val.programmaticStreamSerializationAllowed = 1;

    cudaLaunchConfig_t cfg = {};
    cfg.gridDim  = dim3(NCELL / 1024, C / CCHUNK, B);
    cfg.blockDim = dim3(256, 1, 1);
    cfg.dynamicSmemBytes = 0;
    cfg.stream   = 0;
    cfg.attrs    = attr;
    cfg.numAttrs = 1;

    cudaError_t err = cudaLaunchKernelEx(&cfg, bev_write_kernel<T>,
                                         emb, coords, mask, (const T*)inv, out, BP, P, C);
    if (err != cudaSuccess) {
        // fallback: plain serialized launch
        bev_write_kernel<T><<<cfg.gridDim, cfg.blockDim>>>(emb, coords, mask,
                                                           (const T*)inv, out, BP, P, C);
    }
}

extern "C" void kernel_launch(void* const* d_in, const int* in_sizes, int n_in,
                              void* d_out, int out_size)
{
    const float* emb    = (const float*)d_in[0];   // [B, P, C] f32
    const int*   coords = (const int*)  d_in[1];   // [B, P, 2] i32
    const int*   mask   = (const int*)  d_in[2];   // [B, P]    i32

    int BP = in_sizes[2];                 // B*P
    int C  = in_sizes[0] / BP;            // 64
    int B  = out_size / (C * NCELL);      // 4
    int P  = BP / B;

    float* out = (float*)d_out;

    if (BP + 1 <= 65535) {
        unsigned short* inv = nullptr;
        cudaGetSymbolAddress((void**)&inv, g_inv16);
        launch_path<unsigned short>(emb, coords, mask, inv, out, BP, P, C, B);
    } else {
        int* inv = nullptr;
        cudaGetSymbolAddress((void**)&inv, g_inv32);
        launch_path<int>(emb, coords, mask, inv, out, BP, P, C, B);
    }
}